// round 1
// baseline (speedup 1.0000x reference)
#include <cuda_runtime.h>
#include <cuda_bf16.h>

// TrafficAugmentation: per-row burst simulation.
// Row layout [B=2048, S=4096]. Output f32 [B, S, 1].
//
// Phase 2: for every position s, compute (as if a burst starts at s):
//          nxt = index after burst end, count = output slots emitted,
//          kill = (x[s] <= 0). Exact sequential f32 arithmetic.
// Phase 3: single-thread serial chain walk from s=0 through nxt[] in SMEM,
//          recording (burst start, exclusive output-prefix) pairs.
// Phase 4: parallel over bursts: recompute buf (same order -> identical fp),
//          scatter MSS run + remainder into SMEM output row.
// Phase 5: coalesced store of the row.

#define SS 4096
#define MSSF 1448.0f
#define KILLBIT 0x80000000u

__global__ __launch_bounds__(256)
void traffic_kernel(const float* __restrict__ x,
                    const float* __restrict__ dly,
                    const float* __restrict__ rtt,
                    float* __restrict__ out)
{
    // s_packed: bits [0,13) = nxt (<= 4096), bits [13,27) = count (<= 8340), bit 31 = kill.
    // Aliased as the f32 output-row staging buffer in phases 4/5 (dead after walk).
    __shared__ unsigned int s_packed[SS];
    // s_blist[i]: bits [0,13) = burst start s, bits [13,27) = exclusive output prefix.
    // Entry nb is a sentinel holding the end position of the last burst's range.
    __shared__ unsigned int s_blist[SS + 1];
    __shared__ int s_nb;

    const int row = blockIdx.x;
    const long long base = (long long)row * SS;
    const float* xr = x   + base;
    const float* dr = dly + base;
    const float* rr = rtt + base;
    const int tid = threadIdx.x;
    const int nt  = blockDim.x;

    // ---- Phase 2: per-position burst descriptor -------------------------
    for (int s = tid; s < SS; s += nt) {
        float xs = __ldg(xr + s);
        unsigned int w;
        if (!(xs > 0.0f)) {
            w = KILLBIT;   // outer-while kill: burst start with x <= 0
        } else {
            float r   = __ldg(rr + s);
            float buf = 0.0f;
            int j = s;
            // burst consumes packets j = s..e, where e is first j with
            // (r - sum delays) <= 0; exact sequential f32 order.
            while (true) {
                r   = __fsub_rn(r,   __ldg(dr + j));
                buf = __fadd_rn(buf, __ldg(xr + j));
                j++;
                if (r <= 0.0f || j >= SS) break;
            }
            int n_full = (int)ceilf(__fdiv_rn(buf, MSSF)) - 1;
            if (n_full < 0) n_full = 0;
            float rem = __fsub_rn(buf, __fmul_rn((float)n_full, MSSF));
            int count = n_full + (rem > 0.0f ? 1 : 0);
            w = (unsigned int)j | ((unsigned int)count << 13);
        }
        s_packed[s] = w;
    }
    __syncthreads();

    // ---- Phase 3: serial chain walk (one thread) ------------------------
    if (tid == 0) {
        int s = 0, outpos = 0, nb = 0;
        while (s < SS) {
            unsigned int w = s_packed[s];
            if (w & KILLBIT) break;                   // killed: nothing more consumed
            s_blist[nb++] = (unsigned int)s | ((unsigned int)outpos << 13);
            outpos += (int)((w >> 13) & 0x3FFFu);
            s = (int)(w & 0x1FFFu);
        }
        s_blist[nb] = (unsigned int)s;                // sentinel: end of last range
        s_nb = nb;
    }
    __syncthreads();

    // ---- Phase 4: build output row in SMEM (alias s_packed) -------------
    float* outrow = (float*)s_packed;
    for (int i = tid; i < SS; i += nt) outrow[i] = 0.0f;
    __syncthreads();

    const int nb = s_nb;
    for (int i = tid; i < nb; i += nt) {
        unsigned int b  = s_blist[i];
        int s0 = (int)(b & 0x1FFFu);
        int o  = (int)(b >> 13);
        int e1 = (int)(s_blist[i + 1] & 0x1FFFu);     // burst range [s0, e1)

        // recompute buf in identical order -> bit-identical to phase 2
        float buf = 0.0f;
        for (int j = s0; j < e1; j++) buf = __fadd_rn(buf, __ldg(xr + j));

        int n_full = (int)ceilf(__fdiv_rn(buf, MSSF)) - 1;
        if (n_full < 0) n_full = 0;
        float rem = __fsub_rn(buf, __fmul_rn((float)n_full, MSSF));

        int lim = n_full;
        if (o + lim > SS) lim = SS - o;               // truncation at row end
        for (int k = 0; k < lim; k++) outrow[o + k] = MSSF;
        int rp = o + n_full;
        if (rem > 0.0f && rp < SS) outrow[rp] = rem;  // remainder after MSS run
    }
    __syncthreads();

    // ---- Phase 5: coalesced store ---------------------------------------
    for (int i = tid; i < SS; i += nt) out[base + i] = outrow[i];
}

extern "C" void kernel_launch(void* const* d_in, const int* in_sizes, int n_in,
                              void* d_out, int out_size)
{
    const float* x   = (const float*)d_in[0];
    const float* dly = (const float*)d_in[1];
    const float* rtt = (const float*)d_in[2];
    float* out = (float*)d_out;

    int B = in_sizes[0] / SS;
    traffic_kernel<<<B, 256>>>(x, dly, rtt, out);
}

// round 2
// speedup vs baseline: 1.6123x; 1.6123x over previous
#include <cuda_runtime.h>
#include <cuda_bf16.h>

// TrafficAugmentation [B=2048, S=4096] -> [B, S, 1] f32.
//
// Per row (one block):
//  P0: stage x, dly into SMEM (coalesced float4).
//  P1: for every s, delay-countdown walk (exact fsub chain, 4-way load
//      batching) -> nxt[s] = index after burst end (u16), kill flag.
//  P2: per 32-wide chunk, backward scan -> exit[s] = first chain node
//      beyond s's chunk (nxt strictly increasing makes this exact).
//  P3: serial top walk over <=128 chunk hops -> enter position per chunk.
//  P4: per chunk (parallel): walk bursts, recompute buf in exact index
//      order, accumulate output-slot count.
//  P5: exclusive scan of chunk counts; zero output row.
//  P6: per chunk (parallel): re-walk, emit MSS runs + remainder at
//      private offsets (disjoint ranges, no races).
//  P7: coalesced float4 store.

#define SS     4096
#define CHUNK  32
#define NCHUNK (SS / CHUNK)
#define MSSF   1448.0f
#define KILL16 0x8000u
#define NT     256

__global__ __launch_bounds__(NT)
void traffic_kernel(const float* __restrict__ x,
                    const float* __restrict__ dly,
                    const float* __restrict__ rtt,
                    float* __restrict__ out)
{
    __shared__ __align__(16) float sx[SS + 4];        // x row (+0-pad)
    __shared__ __align__(16) float sd[SS + 4];        // dly row (+big-pad); aliased:
                                                      //   P2/P3: exit table (u16)
                                                      //   P5..P7: output row (f32)
    __shared__ unsigned short snxt[SS];               // burst-end index | kill
    __shared__ unsigned short senter[NCHUNK];         // chain entry pos per chunk
    __shared__ int schunkcnt[NCHUNK];                 // count -> exclusive offset

    const int row = blockIdx.x;
    const size_t base = (size_t)row * SS;
    const int tid = threadIdx.x;

    // ---- P0: stage inputs ------------------------------------------------
    {
        const float4* x4 = (const float4*)(x + base);
        const float4* d4 = (const float4*)(dly + base);
        float4* sx4 = (float4*)sx;
        float4* sd4 = (float4*)sd;
        #pragma unroll
        for (int i = tid; i < SS / 4; i += NT) { sx4[i] = x4[i]; sd4[i] = d4[i]; }
        if (tid < 4) { sx[SS + tid] = 0.0f; sd[SS + tid] = 1e30f; }
    }
    __syncthreads();

    // ---- P1: per-position burst end (exact sequential fsub, batch-4) -----
    for (int s = tid; s < SS; s += NT) {
        unsigned short w;
        if (!(sx[s] > 0.0f)) {
            w = (unsigned short)KILL16;               // outer-while kill
        } else {
            float r = __ldg(rtt + base + s);
            int j = s;
            while (true) {
                // 4 speculative loads (addresses independent of r)
                float d0 = sd[j], d1 = sd[j + 1], d2 = sd[j + 2], d3 = sd[j + 3];
                float r0 = __fsub_rn(r,  d0);
                float r1 = __fsub_rn(r0, d1);
                float r2 = __fsub_rn(r1, d2);
                float r3 = __fsub_rn(r2, d3);
                if (r0 <= 0.0f) { j += 1; break; }
                if (r1 <= 0.0f) { j += 2; break; }
                if (r2 <= 0.0f) { j += 3; break; }
                j += 4;
                if (r3 <= 0.0f) break;
                r = r3;
                // pads (1e30) force termination at/after j == SS
            }
            w = (unsigned short)(j < SS ? j : SS);
        }
        snxt[s] = w;
    }
    __syncthreads();

    // ---- P2: per-chunk exit table (backward scan; nxt strictly increases)
    unsigned short* sexit = (unsigned short*)sd;      // dly is dead
    if (tid < NCHUNK) {
        const int c = tid;
        const int end = (c + 1) * CHUNK;
        for (int s = end - 1; s >= c * CHUNK; s--) {
            unsigned short w = snxt[s];
            unsigned short e;
            if (w & KILL16)       e = (unsigned short)SS;   // chain dies here
            else if ((int)w >= end) e = w;                  // leaves chunk
            else                  e = sexit[w];             // compose within chunk
            sexit[s] = e;
        }
    }
    __syncthreads();

    // ---- P3: serial top walk (<= NCHUNK dependent hops) ------------------
    if (tid == 0) {
        int pos = 0;
        #pragma unroll 4
        for (int c = 0; c < NCHUNK; c++) {
            senter[c] = (unsigned short)pos;
            if (pos < (c + 1) * CHUNK) pos = sexit[pos];  // pos is in chunk c
        }
    }
    __syncthreads();

    // ---- P4: per-chunk output-slot count ---------------------------------
    if (tid < NCHUNK) {
        const int c = tid;
        const int end = (c + 1) * CHUNK;
        int s = senter[c];                                 // may be >= end (empty)
        int total = 0;
        while (s < end) {
            unsigned short w = snxt[s];
            if (w & KILL16) break;
            const int e1 = (int)w;
            float buf = 0.0f;                              // exact index-order sum
            for (int j = s; j < e1; j++) buf = __fadd_rn(buf, sx[j]);
            int nf = (int)ceilf(__fdiv_rn(buf, MSSF)) - 1;
            if (nf < 0) nf = 0;
            float rem = __fsub_rn(buf, __fmul_rn((float)nf, MSSF));
            total += nf + (rem > 0.0f ? 1 : 0);
            s = e1;
        }
        schunkcnt[c] = total;
    }
    __syncthreads();

    // ---- P5: exclusive scan of chunk counts + zero output row ------------
    if (tid == 0) {
        int acc = 0;
        for (int c = 0; c < NCHUNK; c++) {
            int t = schunkcnt[c]; schunkcnt[c] = acc; acc += t;
        }
    }
    float* outrow = sd;                                    // exit table is dead
    for (int i = tid; i < SS; i += NT) outrow[i] = 0.0f;
    __syncthreads();

    // ---- P6: per-chunk emission (disjoint output ranges) -----------------
    if (tid < NCHUNK) {
        const int c = tid;
        const int end = (c + 1) * CHUNK;
        int s = senter[c];
        int o = schunkcnt[c];
        while (s < end) {
            unsigned short w = snxt[s];
            if (w & KILL16) break;
            const int e1 = (int)w;
            float buf = 0.0f;                              // identical order -> identical fp
            for (int j = s; j < e1; j++) buf = __fadd_rn(buf, sx[j]);
            int nf = (int)ceilf(__fdiv_rn(buf, MSSF)) - 1;
            if (nf < 0) nf = 0;
            float rem = __fsub_rn(buf, __fmul_rn((float)nf, MSSF));
            int lim = nf;
            if (o + lim > SS) lim = SS - o;                 // truncation (may be <0)
            for (int k = 0; k < lim; k++) outrow[o + k] = MSSF;
            if (rem > 0.0f && o + nf < SS) outrow[o + nf] = rem;
            o += nf + (rem > 0.0f ? 1 : 0);
            s = e1;
        }
    }
    __syncthreads();

    // ---- P7: coalesced store --------------------------------------------
    {
        float4* o4 = (float4*)(out + base);
        const float4* s4 = (const float4*)outrow;
        #pragma unroll
        for (int i = tid; i < SS / 4; i += NT) o4[i] = s4[i];
    }
}

extern "C" void kernel_launch(void* const* d_in, const int* in_sizes, int n_in,
                              void* d_out, int out_size)
{
    const float* x   = (const float*)d_in[0];
    const float* dly = (const float*)d_in[1];
    const float* rtt = (const float*)d_in[2];
    float* out = (float*)d_out;

    int B = in_sizes[0] / SS;
    traffic_kernel<<<B, NT>>>(x, dly, rtt, out);
}